// round 3
// baseline (speedup 1.0000x reference)
#include <cuda_runtime.h>
#include <cuda_bf16.h>

// GCN 2-layer, minimal-traffic formulation:
//   y[i]   = x[i] * dinv[i]  (5 floats padded to 8 = one 32B L2 sector)
//   z[d]   = sum_edges y[src]          (red.v4 + red.f32, 2 atomics/edge)
//   zt     = z*dinv + x*dinv^2 ; h = relu(zt@W1+b1) ; s = h.W2
//   t[i]   = s[i]*dinv[i]
//   acc[d] = sum_edges t[src]          (1 atomic/edge)
//   out[i] = acc[i]*dinv[i] + s[i]*dinv[i]^2 + b2

#define MAXN 131072
#define IN_DIM 5
#define PAD 8
#define HID 128

__device__ float g_deg[MAXN];
__device__ float g_dinv[MAXN];
__device__ __align__(128) float g_y[MAXN * PAD];
__device__ __align__(128) float g_z[MAXN * PAD];
__device__ float g_t[MAXN];
__device__ float g_acc[MAXN];

__device__ __forceinline__ void red_v4(float* p, float a, float b, float c, float d) {
    asm volatile("red.global.add.v4.f32 [%0], {%1, %2, %3, %4};"
                 :: "l"(p), "f"(a), "f"(b), "f"(c), "f"(d) : "memory");
}

// ---- degree: 4 edges/thread, int4 index load ----
__global__ void k_degree(const int* __restrict__ dst, int E) {
    int t = blockIdx.x * blockDim.x + threadIdx.x;
    int base = t * 4;
    if (base + 3 < E) {
        int4 d4 = *(const int4*)(dst + base);
        atomicAdd(&g_deg[d4.x], 1.0f);
        atomicAdd(&g_deg[d4.y], 1.0f);
        atomicAdd(&g_deg[d4.z], 1.0f);
        atomicAdd(&g_deg[d4.w], 1.0f);
    } else {
        for (int e = base; e < E; e++) atomicAdd(&g_deg[dst[e]], 1.0f);
    }
}

// ---- dinv + scaled padded features ----
__global__ void k_prep(const float* __restrict__ x, int n) {
    int i = blockIdx.x * blockDim.x + threadIdx.x;
    if (i >= n) return;
    float di = rsqrtf(g_deg[i] + 1.0f);
    g_dinv[i] = di;
    float y0 = x[i * IN_DIM + 0] * di;
    float y1 = x[i * IN_DIM + 1] * di;
    float y2 = x[i * IN_DIM + 2] * di;
    float y3 = x[i * IN_DIM + 3] * di;
    float y4 = x[i * IN_DIM + 4] * di;
    *(float4*)&g_y[i * PAD] = make_float4(y0, y1, y2, y3);
    *(float4*)&g_y[i * PAD + 4] = make_float4(y4, 0.f, 0.f, 0.f);
}

// ---- edge pass 1: z[dst] += y[src], 4 edges/thread ----
__global__ void k_edge_agg1(const int* __restrict__ src, const int* __restrict__ dst, int E) {
    int t = blockIdx.x * blockDim.x + threadIdx.x;
    int base = t * 4;
    if (base + 3 < E) {
        int4 s4 = *(const int4*)(src + base);
        int4 d4 = *(const int4*)(dst + base);
        // issue all gathers first (MLP), then all reductions
        float4 a0 = *(const float4*)&g_y[s4.x * PAD];
        float4 a1 = *(const float4*)&g_y[s4.y * PAD];
        float4 a2 = *(const float4*)&g_y[s4.z * PAD];
        float4 a3 = *(const float4*)&g_y[s4.w * PAD];
        float h0 = g_y[s4.x * PAD + 4];
        float h1 = g_y[s4.y * PAD + 4];
        float h2 = g_y[s4.z * PAD + 4];
        float h3 = g_y[s4.w * PAD + 4];
        red_v4(&g_z[d4.x * PAD], a0.x, a0.y, a0.z, a0.w);
        red_v4(&g_z[d4.y * PAD], a1.x, a1.y, a1.z, a1.w);
        red_v4(&g_z[d4.z * PAD], a2.x, a2.y, a2.z, a2.w);
        red_v4(&g_z[d4.w * PAD], a3.x, a3.y, a3.z, a3.w);
        atomicAdd(&g_z[d4.x * PAD + 4], h0);
        atomicAdd(&g_z[d4.y * PAD + 4], h1);
        atomicAdd(&g_z[d4.z * PAD + 4], h2);
        atomicAdd(&g_z[d4.w * PAD + 4], h3);
    } else {
        for (int e = base; e < E; e++) {
            int s = src[e], d = dst[e];
            float4 a = *(const float4*)&g_y[s * PAD];
            float h = g_y[s * PAD + 4];
            red_v4(&g_z[d * PAD], a.x, a.y, a.z, a.w);
            atomicAdd(&g_z[d * PAD + 4], h);
        }
    }
}

// ---- per-node MLP ----
__global__ void k_node(const float* __restrict__ x,
                       const float* __restrict__ W1, const float* __restrict__ b1,
                       const float* __restrict__ W2, const float* __restrict__ b2,
                       float* __restrict__ out, int n) {
    __shared__ float sW1[IN_DIM * HID];
    __shared__ float sb1[HID];
    __shared__ float sW2[HID];
    for (int i = threadIdx.x; i < IN_DIM * HID; i += blockDim.x) sW1[i] = W1[i];
    if (threadIdx.x < HID) {
        sb1[threadIdx.x] = b1[threadIdx.x];
        sW2[threadIdx.x] = W2[threadIdx.x];
    }
    __syncthreads();

    int i = blockIdx.x * blockDim.x + threadIdx.x;
    if (i >= n) return;

    float di = g_dinv[i];
    float d2 = di * di;
    float zt[IN_DIM];
#pragma unroll
    for (int j = 0; j < IN_DIM; j++) {
        zt[j] = g_z[i * PAD + j] * di + x[i * IN_DIM + j] * d2;
    }

    float s = 0.0f;
#pragma unroll 8
    for (int k = 0; k < HID; k++) {
        float acc = sb1[k];
#pragma unroll
        for (int j = 0; j < IN_DIM; j++) acc = fmaf(zt[j], sW1[j * HID + k], acc);
        acc = fmaxf(acc, 0.0f);
        s = fmaf(acc, sW2[k], s);
    }
    g_t[i] = s * di;
    out[i] = s * d2 + b2[0];
}

// ---- edge pass 2: acc[dst] += t[src], 4 edges/thread ----
__global__ void k_edge_agg2(const int* __restrict__ src, const int* __restrict__ dst, int E) {
    int t = blockIdx.x * blockDim.x + threadIdx.x;
    int base = t * 4;
    if (base + 3 < E) {
        int4 s4 = *(const int4*)(src + base);
        int4 d4 = *(const int4*)(dst + base);
        float t0 = g_t[s4.x];
        float t1 = g_t[s4.y];
        float t2 = g_t[s4.z];
        float t3 = g_t[s4.w];
        atomicAdd(&g_acc[d4.x], t0);
        atomicAdd(&g_acc[d4.y], t1);
        atomicAdd(&g_acc[d4.z], t2);
        atomicAdd(&g_acc[d4.w], t3);
    } else {
        for (int e = base; e < E; e++) atomicAdd(&g_acc[dst[e]], g_t[src[e]]);
    }
}

__global__ void k_final(float* __restrict__ out, int n) {
    int i = blockIdx.x * blockDim.x + threadIdx.x;
    if (i >= n) return;
    out[i] += g_acc[i] * g_dinv[i];
}

extern "C" void kernel_launch(void* const* d_in, const int* in_sizes, int n_in,
                              void* d_out, int out_size) {
    const float* x  = (const float*)d_in[0];
    const int* ei   = (const int*)d_in[1];   // [2, E]: src row then dst row
    const float* W1 = (const float*)d_in[2];
    const float* b1 = (const float*)d_in[3];
    const float* W2 = (const float*)d_in[4];
    const float* b2 = (const float*)d_in[5];
    float* out = (float*)d_out;

    int n = in_sizes[0] / IN_DIM;
    int E = in_sizes[1] / 2;
    const int* src = ei;
    const int* dst = ei + E;

    // zero scratch via memset nodes (graph-capturable, no alloc)
    void *p_deg, *p_z, *p_acc;
    cudaGetSymbolAddress(&p_deg, g_deg);
    cudaGetSymbolAddress(&p_z, g_z);
    cudaGetSymbolAddress(&p_acc, g_acc);
    cudaMemsetAsync(p_deg, 0, (size_t)n * sizeof(float));
    cudaMemsetAsync(p_z, 0, (size_t)n * PAD * sizeof(float));
    cudaMemsetAsync(p_acc, 0, (size_t)n * sizeof(float));

    const int TB = 256;
    int gb_n = (n + TB - 1) / TB;
    int gb_e4 = (E + TB * 4 - 1) / (TB * 4);

    k_degree<<<gb_e4, TB>>>(dst, E);
    k_prep<<<gb_n, TB>>>(x, n);
    k_edge_agg1<<<gb_e4, TB>>>(src, dst, E);
    k_node<<<gb_n, TB>>>(x, W1, b1, W2, b2, out, n);
    k_edge_agg2<<<gb_e4, TB>>>(src, dst, E);
    k_final<<<gb_n, TB>>>(out, n);
}